// round 1
// baseline (speedup 1.0000x reference)
#include <cuda_runtime.h>
#include <math.h>

#define N_NODES 20000
#define D       256
#define E_EDGES 500000

// ---------------- scratch (no allocations allowed) ----------------
__device__ float g_agg[N_NODES * D];
__device__ float g_cnt[N_NODES];
__device__ float g_inv[N_NODES];
__device__ float g_h  [N_NODES * D];
__device__ float g_e0 [N_NODES * D];
__device__ float g_e1 [N_NODES * D];
__device__ float g_f1 [N_NODES * D];

// ---------------- zero agg + cnt ----------------
__global__ void zero_kernel(float* __restrict__ agg, float* __restrict__ cnt,
                            int n_agg, int n_cnt) {
    int i  = blockIdx.x * blockDim.x + threadIdx.x;
    int st = gridDim.x * blockDim.x;
    for (int j = i; j < n_agg; j += st) agg[j] = 0.0f;
    for (int j = i; j < n_cnt; j += st) cnt[j] = 0.0f;
}

// ---------------- edge aggregation: one warp per edge ----------------
// agg[src] += h[dst] for edges with edge_type == rel; cnt[src] += 1
__global__ void agg_kernel(const int* __restrict__ ei, const int* __restrict__ et,
                           const float* __restrict__ h,
                           float* __restrict__ agg, float* __restrict__ cnt,
                           int rel, int E) {
    int w    = (blockIdx.x * blockDim.x + threadIdx.x) >> 5;
    int lane = threadIdx.x & 31;
    if (w >= E) return;
    if (et[w] != rel) return;
    int s = ei[w];
    int d = ei[E + w];
    const float* hrow = h   + (size_t)d * D;
    float*       arow = agg + (size_t)s * D;
#pragma unroll
    for (int i = 0; i < 8; i++) {
        atomicAdd(&arow[lane + 32 * i], hrow[lane + 32 * i]);
    }
    if (lane == 0) atomicAdd(&cnt[s], 1.0f);
}

// ---------------- inv[i] = 1 / max(cnt[i], 1) ----------------
__global__ void inv_kernel(const float* __restrict__ cnt, float* __restrict__ inv, int n) {
    int i = blockIdx.x * blockDim.x + threadIdx.x;
    if (i < n) inv[i] = 1.0f / fmaxf(cnt[i], 1.0f);
}

// ---------------- dual-A GEMM: C = act(A1s @ B1 + A2 @ B2 + bias) ----------------
// A1, A2: [M,256].  A1 rows optionally scaled by scale1[row] (pass null to skip).
// B1, B2: [256,256] row-major.  Conceptually C = [A1s | A2] @ [B1; B2], K=512.
// BM=128, BN=128, BK=16, 256 threads, 8x8 per thread.
#define BM 128
#define BN 128
#define BK 16

__global__ __launch_bounds__(256, 2)
void gemm_dual(const float* __restrict__ A1, const float* __restrict__ A2,
               const float* __restrict__ scale1,
               const float* __restrict__ B1, const float* __restrict__ B2,
               const float* __restrict__ bias,
               float* __restrict__ C, int M, int do_relu) {
    __shared__ float As[BK][BM + 4];   // transposed A tile (padded)
    __shared__ float Bs[BK][BN];

    const int tid = threadIdx.x;
    const int tx  = tid & 15;          // 0..15 -> 8 cols each
    const int ty  = tid >> 4;          // 0..15 -> 8 rows each
    const int rowBase = blockIdx.y * BM;
    const int colBase = blockIdx.x * BN;

    float acc[8][8];
#pragma unroll
    for (int m = 0; m < 8; m++)
#pragma unroll
        for (int n = 0; n < 8; n++) acc[m][n] = 0.0f;

#pragma unroll 1
    for (int it = 0; it < 512 / BK; it++) {
        const int  kt   = it * BK;
        const bool h1   = (kt < 256);
        const float* A  = h1 ? A1 : A2;
        const float* B  = h1 ? B1 : B2;
        const int  koff = h1 ? kt : (kt - 256);

        // load A tile (128 rows x 16 cols), transpose into As
#pragma unroll
        for (int i = 0; i < 2; i++) {
            int f4 = tid + i * 256;          // 0..511
            int r  = f4 >> 2;                // 0..127
            int c4 = f4 & 3;                 // 0..3
            int gr = rowBase + r;
            float4 v = make_float4(0.f, 0.f, 0.f, 0.f);
            if (gr < M) {
                v = *(const float4*)(A + (size_t)gr * D + koff + c4 * 4);
                if (h1 && scale1) {
                    float s = scale1[gr];
                    v.x *= s; v.y *= s; v.z *= s; v.w *= s;
                }
            }
            As[c4 * 4 + 0][r] = v.x;
            As[c4 * 4 + 1][r] = v.y;
            As[c4 * 4 + 2][r] = v.z;
            As[c4 * 4 + 3][r] = v.w;
        }
        // load B tile (16 rows x 128 cols)
#pragma unroll
        for (int i = 0; i < 2; i++) {
            int f4 = tid + i * 256;          // 0..511
            int r  = f4 >> 5;                // 0..15
            int c4 = f4 & 31;                // 0..31
            float4 v = *(const float4*)(B + (size_t)(koff + r) * D + colBase + c4 * 4);
            *(float4*)&Bs[r][c4 * 4] = v;
        }
        __syncthreads();

#pragma unroll
        for (int k = 0; k < BK; k++) {
            float4 a0 = *(const float4*)&As[k][ty * 8];
            float4 a1 = *(const float4*)&As[k][ty * 8 + 4];
            float4 b0 = *(const float4*)&Bs[k][tx * 8];
            float4 b1 = *(const float4*)&Bs[k][tx * 8 + 4];
            float ra[8] = {a0.x, a0.y, a0.z, a0.w, a1.x, a1.y, a1.z, a1.w};
            float rb[8] = {b0.x, b0.y, b0.z, b0.w, b1.x, b1.y, b1.z, b1.w};
#pragma unroll
            for (int m = 0; m < 8; m++)
#pragma unroll
                for (int n = 0; n < 8; n++)
                    acc[m][n] = fmaf(ra[m], rb[n], acc[m][n]);
        }
        __syncthreads();
    }

    // epilogue: + bias, optional relu, store
    float bv[8];
#pragma unroll
    for (int n = 0; n < 8; n++) bv[n] = bias[colBase + tx * 8 + n];

#pragma unroll
    for (int m = 0; m < 8; m++) {
        int gr = rowBase + ty * 8 + m;
        if (gr >= M) continue;
        float* crow = C + (size_t)gr * D + colBase + tx * 8;
#pragma unroll
        for (int n = 0; n < 8; n++) {
            float v = acc[m][n] + bv[n];
            if (do_relu) v = fmaxf(v, 0.0f);
            acc[m][n] = v;
        }
        *(float4*)(crow)     = make_float4(acc[m][0], acc[m][1], acc[m][2], acc[m][3]);
        *(float4*)(crow + 4) = make_float4(acc[m][4], acc[m][5], acc[m][6], acc[m][7]);
    }
}

// ---------------- fc2 (256->16) + log_softmax, one warp per row ----------------
__global__ void fc2_lsm_kernel(const float* __restrict__ H,
                               const float* __restrict__ W,   // [256,16] row-major
                               const float* __restrict__ b,   // [16]
                               float* __restrict__ out, int M) {
    __shared__ float sw[16 * 256];     // transposed: sw[n*256+k] = W[k*16+n]
    const int tid = threadIdx.x;
    for (int i = tid; i < 16 * 256; i += blockDim.x) {
        int n = i >> 8, k = i & 255;
        sw[i] = W[k * 16 + n];
    }
    __syncthreads();

    const int warp = tid >> 5;
    const int lane = tid & 31;
    const int row  = blockIdx.x * 4 + warp;
    if (row >= M) return;

    const float* hrow = H + (size_t)row * D;
    float acc[16];
#pragma unroll
    for (int n = 0; n < 16; n++) acc[n] = 0.0f;

#pragma unroll
    for (int kk = 0; kk < 8; kk++) {
        int k = lane + 32 * kk;
        float hv = hrow[k];
#pragma unroll
        for (int n = 0; n < 16; n++) acc[n] = fmaf(hv, sw[n * 256 + k], acc[n]);
    }
#pragma unroll
    for (int n = 0; n < 16; n++) {
#pragma unroll
        for (int o = 16; o > 0; o >>= 1)
            acc[n] += __shfl_xor_sync(0xFFFFFFFFu, acc[n], o);
    }
    if (lane == 0) {
        float v[16];
        float mx = -1e30f;
#pragma unroll
        for (int n = 0; n < 16; n++) { v[n] = acc[n] + b[n]; mx = fmaxf(mx, v[n]); }
        float s = 0.0f;
#pragma unroll
        for (int n = 0; n < 16; n++) s += expf(v[n] - mx);
        float l = logf(s);
        float* orow = out + (size_t)row * 16;
#pragma unroll
        for (int n = 0; n < 16; n++) orow[n] = v[n] - mx - l;
    }
}

// ---------------- host ----------------
static float* sym(const void* symbol) {
    void* p = nullptr;
    cudaGetSymbolAddress(&p, symbol);
    return (float*)p;
}

extern "C" void kernel_launch(void* const* d_in, const int* in_sizes, int n_in,
                              void* d_out, int out_size) {
    const float* x     = (const float*)d_in[0];
    const int*   ei    = (const int*)  d_in[1];
    const int*   et    = (const int*)  d_in[2];
    const float* relW  = (const float*)d_in[3];   // [4,5,256,256]
    const float* rootW = (const float*)d_in[4];   // [4,256,256]
    const float* bias  = (const float*)d_in[5];   // [4,256]
    const float* fc1w  = (const float*)d_in[6];   // [512,256]
    const float* fc1b  = (const float*)d_in[7];   // [256]
    const float* fc2w  = (const float*)d_in[8];   // [256,16]
    const float* fc2b  = (const float*)d_in[9];   // [16]
    float* out = (float*)d_out;

    const int M = N_NODES;
    const int E = E_EDGES;

    float* agg = sym(g_agg);
    float* cnt = sym(g_cnt);
    float* inv = sym(g_inv);
    float* h   = sym(g_h);
    float* e0  = sym(g_e0);
    float* e1  = sym(g_e1);
    float* f1  = sym(g_f1);

    const dim3 ggrid(2, (M + BM - 1) / BM);     // (2, 157)
    const int  aggBlocks = (E * 32 + 255) / 256; // 62500
    const int  invBlocks = (M + 255) / 256;

    // conv ci uses relation rel=ci, W = rel_W[ci, ci]
    const float* hin[4]  = { x, h, x, h };
    float*       hout[4] = { h, e0, h, e1 };

    for (int ci = 0; ci < 4; ci++) {
        zero_kernel<<<2048, 256>>>(agg, cnt, M * D, M);
        agg_kernel<<<aggBlocks, 256>>>(ei, et, hin[ci], agg, cnt, ci, E);
        inv_kernel<<<invBlocks, 256>>>(cnt, inv, M);
        const float* Wc = relW + ((size_t)ci * 5 + ci) * D * D;
        const float* Rc = rootW + (size_t)ci * D * D;
        const float* bc = bias + (size_t)ci * D;
        gemm_dual<<<ggrid, 256>>>(agg, hin[ci], inv, Wc, Rc, bc, hout[ci], M, 1);
    }

    // fc1: [e0 | e1] @ [fc1w_top; fc1w_bot] + fc1b, relu
    gemm_dual<<<ggrid, 256>>>(e0, e1, nullptr, fc1w, fc1w + 256 * 256, fc1b, f1, M, 1);

    // fc2 + log_softmax
    fc2_lsm_kernel<<<(M + 3) / 4, 128>>>(f1, fc2w, fc2b, out, M);
}

// round 3
// speedup vs baseline: 1.5794x; 1.5794x over previous
#include <cuda_runtime.h>
#include <cuda_bf16.h>
#include <mma.h>
#include <cstdint>
#include <math.h>

using namespace nvcuda;

#define N_NODES 20000
#define D       256
#define E_EDGES 500000
#define NGEMM   5

// ---------------- scratch (no allocations allowed) ----------------
__device__ float g_agg[N_NODES * D];
__device__ float g_cnt[N_NODES];
__device__ float g_h  [N_NODES * D];
__device__ float g_f1 [N_NODES * D];
__device__ __nv_bfloat16 g_xhi[N_NODES * D], g_xlo[N_NODES * D];
__device__ __nv_bfloat16 g_hhi[N_NODES * D], g_hlo[N_NODES * D];
__device__ __nv_bfloat16 g_ahi[N_NODES * D], g_alo[N_NODES * D];
__device__ __nv_bfloat16 g_e0hi[N_NODES * D], g_e0lo[N_NODES * D];
__device__ __nv_bfloat16 g_e1hi[N_NODES * D], g_e1lo[N_NODES * D];
// transposed+split B for all 5 GEMMs: Bt[g][n][k] (n=0..255 out, k=0..511 in)
__device__ __nv_bfloat16 g_Bhi[NGEMM * 256 * 512], g_Blo[NGEMM * 256 * 512];

// ================= helpers =================
__device__ __forceinline__ uint32_t smem_u32(const void* p) {
    uint32_t a;
    asm("{ .reg .u64 t; cvta.to.shared.u64 t, %1; cvt.u32.u64 %0, t; }" : "=r"(a) : "l"(p));
    return a;
}
__device__ __forceinline__ void cp16(uint32_t dst, const void* src, bool valid) {
    int sz = valid ? 16 : 0;
    asm volatile("cp.async.cg.shared.global [%0], [%1], 16, %2;"
                 :: "r"(dst), "l"(__cvta_generic_to_global(src)), "r"(sz) : "memory");
}
#define CP_COMMIT() asm volatile("cp.async.commit_group;" ::: "memory")
#define CP_WAIT(n)  asm volatile("cp.async.wait_group %0;" :: "n"(n) : "memory")

// ================= small kernels =================
__global__ void zero_kernel(float* __restrict__ agg, float* __restrict__ cnt,
                            int n_agg, int n_cnt) {
    int i = blockIdx.x * blockDim.x + threadIdx.x;
    int st = gridDim.x * blockDim.x;
    for (int j = i; j < n_agg; j += st) agg[j] = 0.0f;
    for (int j = i; j < n_cnt; j += st) cnt[j] = 0.0f;
}

__global__ void agg_kernel(const int* __restrict__ ei, const int* __restrict__ et,
                           const float* __restrict__ h,
                           float* __restrict__ agg, float* __restrict__ cnt,
                           int rel, int E) {
    int w = (blockIdx.x * blockDim.x + threadIdx.x) >> 5;
    int lane = threadIdx.x & 31;
    if (w >= E) return;
    if (et[w] != rel) return;
    int s = ei[w];
    int d = ei[E + w];
    const float* hrow = h + (size_t)d * D;
    float* arow = agg + (size_t)s * D;
#pragma unroll
    for (int i = 0; i < 8; i++)
        atomicAdd(&arow[lane + 32 * i], hrow[lane + 32 * i]);
    if (lane == 0) atomicAdd(&cnt[s], 1.0f);
}

// fp32 -> bf16 hi/lo split, optional per-row mean scaling by 1/max(cnt,1)
__global__ void conv_hilo(const float* __restrict__ src, const float* __restrict__ cnt,
                          __nv_bfloat16* __restrict__ hi, __nv_bfloat16* __restrict__ lo, int n) {
    int i = blockIdx.x * blockDim.x + threadIdx.x;
    if (i >= n) return;
    float v = src[i];
    if (cnt) v *= (1.0f / fmaxf(cnt[i >> 8], 1.0f));
    __nv_bfloat16 h = __float2bfloat16(v);
    hi[i] = h;
    lo[i] = __float2bfloat16(v - __bfloat162float(h));
}

// build transposed+split B for all 5 GEMMs: Bt[g][n][k]
__global__ void conv_B(const float* __restrict__ relW, const float* __restrict__ rootW,
                       const float* __restrict__ fc1w,
                       __nv_bfloat16* __restrict__ Bhi, __nv_bfloat16* __restrict__ Blo) {
    int i = blockIdx.x * blockDim.x + threadIdx.x;
    if (i >= NGEMM * 256 * 512) return;
    int g = i >> 17;
    int rem = i & 131071;
    int n = rem >> 9;
    int k = rem & 511;
    float v;
    if (g < 4) {
        v = (k < 256) ? relW[((size_t)g * 5 + g) * 65536 + (size_t)k * 256 + n]
                      : rootW[(size_t)g * 65536 + (size_t)(k - 256) * 256 + n];
    } else {
        v = fc1w[(size_t)k * 256 + n];
    }
    __nv_bfloat16 h = __float2bfloat16(v);
    Bhi[i] = h;
    Blo[i] = __float2bfloat16(v - __bfloat162float(h));
}

// ================= WMMA bf16 split GEMM =================
// C[M,256] = relu( [A1|A2](fp32 via hi/lo split) @ Bt^T + bias ), K=512, 3 passes.
// CTA tile 128x128, 8 warps (2x4), warp tile 64x32. KC=32, double-buffered cp.async.
// SMEM: As/Bs per buffer: 128 rows x 40 bf16 (80B stride, conflict-free) = 10240B each.
// buf0: A@0 B@10240 ; buf1: A@20480 B@30720. Epilogue reuses smem as float C tile
// (64 rows x 132 floats = 33792B), done in two 64-row halves.
#define SMEM_BYTES 40960
#define NCHUNK 48

__global__ __launch_bounds__(256, 2)
void gemm_wmma(const __nv_bfloat16* __restrict__ A1hi, const __nv_bfloat16* __restrict__ A1lo,
               const __nv_bfloat16* __restrict__ A2hi, const __nv_bfloat16* __restrict__ A2lo,
               const __nv_bfloat16* __restrict__ Bhi, const __nv_bfloat16* __restrict__ Blo,
               const float* __restrict__ bias,
               float* __restrict__ Cf, __nv_bfloat16* __restrict__ Chi, __nv_bfloat16* __restrict__ Clo,
               int M) {
    extern __shared__ __align__(16) char smem[];
    const uint32_t sb = smem_u32(smem);
    const int tid = threadIdx.x;
    const int wid = tid >> 5;
    const int wm = wid >> 2;          // 0..1 (64-row half)
    const int wn = wid & 3;           // 0..3 (32-col slice)
    const int row0 = blockIdx.x * 128;
    const int col0 = blockIdx.y * 128;

    wmma::fragment<wmma::accumulator, 16, 16, 16, float> acc[4][2];
#pragma unroll
    for (int mi = 0; mi < 4; mi++)
#pragma unroll
        for (int ni = 0; ni < 2; ni++) wmma::fill_fragment(acc[mi][ni], 0.0f);

    // per-thread load coords: 2 x 16B per tile per chunk
    const int r_ld = tid >> 2;                 // reused with +64 offset
    const int q_ld = tid & 3;

    auto issue = [&](int c) {
        const int b = c & 1;
        const int p = c >> 4;                  // 0: hi*Bhi, 1: hi*Blo, 2: lo*Bhi
        const int kglob = (c & 15) * 32;
        const __nv_bfloat16* Aph = (p == 2) ? A1lo : A1hi;
        const __nv_bfloat16* Ap2 = (p == 2) ? A2lo : A2hi;
        const __nv_bfloat16* Ap = (kglob < 256) ? Aph : Ap2;
        const int koff = kglob & 255;
        const __nv_bfloat16* Bp = (p == 1) ? Blo : Bhi;
        const uint32_t abase = sb + b * 20480;
        const uint32_t bbase = abase + 10240;
#pragma unroll
        for (int i = 0; i < 2; i++) {
            int r = r_ld + i * 64;
            bool v = (row0 + r) < M;
            const __nv_bfloat16* asrc = Ap + (size_t)(v ? (row0 + r) : 0) * 256 + koff + q_ld * 8;
            cp16(abase + r * 80 + q_ld * 16, asrc, v);
            const __nv_bfloat16* bsrc = Bp + (size_t)(col0 + r) * 512 + kglob + q_ld * 8;
            cp16(bbase + r * 80 + q_ld * 16, bsrc, true);
        }
    };

    issue(0);
    CP_COMMIT();

#pragma unroll 1
    for (int c = 0; c < NCHUNK; c++) {
        if (c < NCHUNK - 1) {
            issue(c + 1);
            CP_COMMIT();
            CP_WAIT(1);
        } else {
            CP_WAIT(0);
        }
        __syncthreads();

        const int b = c & 1;
        const __nv_bfloat16* As = (const __nv_bfloat16*)(smem + b * 20480);
        const __nv_bfloat16* Bs = (const __nv_bfloat16*)(smem + b * 20480 + 10240);
#pragma unroll
        for (int kk = 0; kk < 2; kk++) {
            wmma::fragment<wmma::matrix_a, 16, 16, 16, __nv_bfloat16, wmma::row_major> af[4];
            wmma::fragment<wmma::matrix_b, 16, 16, 16, __nv_bfloat16, wmma::col_major> bf[2];
#pragma unroll
            for (int mi = 0; mi < 4; mi++)
                wmma::load_matrix_sync(af[mi], As + (wm * 64 + mi * 16) * 40 + kk * 16, 40);
#pragma unroll
            for (int ni = 0; ni < 2; ni++)
                wmma::load_matrix_sync(bf[ni], Bs + (wn * 32 + ni * 16) * 40 + kk * 16, 40);
#pragma unroll
            for (int mi = 0; mi < 4; mi++)
#pragma unroll
                for (int ni = 0; ni < 2; ni++)
                    wmma::mma_sync(acc[mi][ni], af[mi], bf[ni], acc[mi][ni]);
        }
        __syncthreads();   // protect buffer reuse by next issue
    }

    // ---------------- epilogue: two 64-row halves through smem ----------------
    float* Cs = (float*)smem;
    const int er = tid >> 2;          // 0..63
    const int ecq = tid & 3;          // col quarter
#pragma unroll 1
    for (int h = 0; h < 2; h++) {
        if (wm == h) {
#pragma unroll
            for (int mi = 0; mi < 4; mi++)
#pragma unroll
                for (int ni = 0; ni < 2; ni++)
                    wmma::store_matrix_sync(Cs + (mi * 16) * 132 + wn * 32 + ni * 16,
                                            acc[mi][ni], 132, wmma::mem_row_major);
        }
        __syncthreads();
        int gr = row0 + h * 64 + er;
        if (gr < M) {
            float v[32];
#pragma unroll
            for (int j = 0; j < 32; j++) {
                int ccol = ecq * 32 + j;
                v[j] = fmaxf(Cs[er * 132 + ccol] + __ldg(&bias[col0 + ccol]), 0.0f);
            }
            if (Cf) {
                float* crow = Cf + (size_t)gr * 256 + col0 + ecq * 32;
#pragma unroll
                for (int j = 0; j < 32; j += 4)
                    *(float4*)(crow + j) = make_float4(v[j], v[j + 1], v[j + 2], v[j + 3]);
            }
            if (Chi) {
                uint32_t ph[16], pl[16];
#pragma unroll
                for (int j = 0; j < 16; j++) {
                    __nv_bfloat16 h0 = __float2bfloat16(v[2 * j]);
                    __nv_bfloat16 h1 = __float2bfloat16(v[2 * j + 1]);
                    __nv_bfloat16 l0 = __float2bfloat16(v[2 * j] - __bfloat162float(h0));
                    __nv_bfloat16 l1 = __float2bfloat16(v[2 * j + 1] - __bfloat162float(h1));
                    ph[j] = (uint32_t)__bfloat16_as_ushort(h0) | ((uint32_t)__bfloat16_as_ushort(h1) << 16);
                    pl[j] = (uint32_t)__bfloat16_as_ushort(l0) | ((uint32_t)__bfloat16_as_ushort(l1) << 16);
                }
                uint32_t* hrow = (uint32_t*)(Chi + (size_t)gr * 256 + col0 + ecq * 32);
                uint32_t* lrow = (uint32_t*)(Clo + (size_t)gr * 256 + col0 + ecq * 32);
#pragma unroll
                for (int j = 0; j < 16; j += 4) {
                    *(uint4*)(hrow + j) = make_uint4(ph[j], ph[j + 1], ph[j + 2], ph[j + 3]);
                    *(uint4*)(lrow + j) = make_uint4(pl[j], pl[j + 1], pl[j + 2], pl[j + 3]);
                }
            }
        }
        __syncthreads();
    }
}

// ---------------- fc2 (256->16) + log_softmax, one warp per row ----------------
__global__ void fc2_lsm_kernel(const float* __restrict__ H,
                               const float* __restrict__ W,   // [256,16] row-major
                               const float* __restrict__ b,   // [16]
                               float* __restrict__ out, int M) {
    __shared__ float sw[16 * 256];
    const int tid = threadIdx.x;
    for (int i = tid; i < 16 * 256; i += blockDim.x) {
        int n = i >> 8, k = i & 255;
        sw[i] = W[k * 16 + n];
    }
    __syncthreads();

    const int warp = tid >> 5;
    const int lane = tid & 31;
    const int row = blockIdx.x * 4 + warp;
    if (row >= M) return;

    const float* hrow = H + (size_t)row * D;
    float acc[16];
#pragma unroll
    for (int n = 0; n < 16; n++) acc[n] = 0.0f;
#pragma unroll
    for (int kk = 0; kk < 8; kk++) {
        int k = lane + 32 * kk;
        float hv = hrow[k];
#pragma unroll
        for (int n = 0; n < 16; n++) acc[n] = fmaf(hv, sw[n * 256 + k], acc[n]);
    }
#pragma unroll
    for (int n = 0; n < 16; n++) {
#pragma unroll
        for (int o = 16; o > 0; o >>= 1)
            acc[n] += __shfl_xor_sync(0xFFFFFFFFu, acc[n], o);
    }
    if (lane == 0) {
        float v[16];
        float mx = -1e30f;
#pragma unroll
        for (int n = 0; n < 16; n++) { v[n] = acc[n] + b[n]; mx = fmaxf(mx, v[n]); }
        float s = 0.0f;
#pragma unroll
        for (int n = 0; n < 16; n++) s += expf(v[n] - mx);
        float l = logf(s);
        float* orow = out + (size_t)row * 16;
#pragma unroll
        for (int n = 0; n < 16; n++) orow[n] = v[n] - mx - l;
    }
}

// ================= host =================
template <typename T>
static T* sym(const void* symbol) {
    void* p = nullptr;
    cudaGetSymbolAddress(&p, symbol);
    return (T*)p;
}

extern "C" void kernel_launch(void* const* d_in, const int* in_sizes, int n_in,
                              void* d_out, int out_size) {
    const float* x     = (const float*)d_in[0];
    const int*   ei    = (const int*)  d_in[1];
    const int*   et    = (const int*)  d_in[2];
    const float* relW  = (const float*)d_in[3];
    const float* rootW = (const float*)d_in[4];
    const float* bias  = (const float*)d_in[5];
    const float* fc1w  = (const float*)d_in[6];
    const float* fc1b  = (const float*)d_in[7];
    const float* fc2w  = (const float*)d_in[8];
    const float* fc2b  = (const float*)d_in[9];
    float* out = (float*)d_out;

    const int M = N_NODES;
    const int E = E_EDGES;

    float* agg = sym<float>(g_agg);
    float* cnt = sym<float>(g_cnt);
    float* h   = sym<float>(g_h);
    float* f1  = sym<float>(g_f1);
    __nv_bfloat16* xhi = sym<__nv_bfloat16>(g_xhi);
    __nv_bfloat16* xlo = sym<__nv_bfloat16>(g_xlo);
    __nv_bfloat16* hhi = sym<__nv_bfloat16>(g_hhi);
    __nv_bfloat16* hlo = sym<__nv_bfloat16>(g_hlo);
    __nv_bfloat16* ahi = sym<__nv_bfloat16>(g_ahi);
    __nv_bfloat16* alo = sym<__nv_bfloat16>(g_alo);
    __nv_bfloat16* e0hi = sym<__nv_bfloat16>(g_e0hi);
    __nv_bfloat16* e0lo = sym<__nv_bfloat16>(g_e0lo);
    __nv_bfloat16* e1hi = sym<__nv_bfloat16>(g_e1hi);
    __nv_bfloat16* e1lo = sym<__nv_bfloat16>(g_e1lo);
    __nv_bfloat16* Bhi = sym<__nv_bfloat16>(g_Bhi);
    __nv_bfloat16* Blo = sym<__nv_bfloat16>(g_Blo);

    const int ND = M * D;
    const int gridND = (ND + 255) / 256;
    const int aggBlocks = (E * 32 + 255) / 256;
    const dim3 ggrid((M + 127) / 128, 2);

    // weight conversion (independent of activations)
    conv_B<<<(NGEMM * 256 * 512 + 255) / 256, 256>>>(relW, rootW, fc1w, Bhi, Blo);
    // x -> hi/lo (used as A2 for convs 0 and 2)
    conv_hilo<<<gridND, 256>>>(x, nullptr, xhi, xlo, ND);

    const float* hin_f32[4] = { x, h, x, h };
    const __nv_bfloat16* a2hi[4] = { xhi, hhi, xhi, hhi };
    const __nv_bfloat16* a2lo[4] = { xlo, hlo, xlo, hlo };
    float* outF[4] = { h, nullptr, h, nullptr };
    __nv_bfloat16* outHi[4] = { hhi, e0hi, hhi, e1hi };
    __nv_bfloat16* outLo[4] = { hlo, e0lo, hlo, e1lo };

    for (int ci = 0; ci < 4; ci++) {
        zero_kernel<<<2048, 256>>>(agg, cnt, ND, M);
        agg_kernel<<<aggBlocks, 256>>>(ei, et, hin_f32[ci], agg, cnt, ci, E);
        conv_hilo<<<gridND, 256>>>(agg, cnt, ahi, alo, ND);
        gemm_wmma<<<ggrid, 256, SMEM_BYTES>>>(
            ahi, alo, a2hi[ci], a2lo[ci],
            Bhi + (size_t)ci * 256 * 512, Blo + (size_t)ci * 256 * 512,
            bias + (size_t)ci * 256,
            outF[ci], outHi[ci], outLo[ci], M);
    }

    // fc1: [e0 | e1] @ fc1w + fc1b, relu -> f1 (fp32 only)
    gemm_wmma<<<ggrid, 256, SMEM_BYTES>>>(
        e0hi, e0lo, e1hi, e1lo,
        Bhi + (size_t)4 * 256 * 512, Blo + (size_t)4 * 256 * 512,
        fc1b, f1, nullptr, nullptr, M);

    // fc2 + log_softmax
    fc2_lsm_kernel<<<(M + 3) / 4, 128>>>(f1, fc2w, fc2b, out, M);
}

// round 4
// speedup vs baseline: 1.9771x; 1.2518x over previous
#include <cuda_runtime.h>
#include <cuda_bf16.h>
#include <mma.h>
#include <cstdint>
#include <math.h>

using namespace nvcuda;

#define NN 20000
#define D  256
#define EE 500000
#define NR 4
#define NBKT (NR * NN)
#define NBLK 157   // row blocks per 20000-row half (128 rows each)

// ---------------- scratch (no allocations allowed) ----------------
__device__ int g_deg[NBKT];
__device__ int g_cur[NBKT];
__device__ int g_rowptr[NBKT + 1];
__device__ int g_adj[EE];

__device__ __nv_bfloat16 g_xhi[NN * D], g_xlo[NN * D];
__device__ __nv_bfloat16 g_agghi[2 * NN * D], g_agglo[2 * NN * D];
__device__ __nv_bfloat16 g_hhi[2 * NN * D], g_hlo[2 * NN * D];
__device__ __nv_bfloat16 g_ehi[2 * NN * D], g_elo[2 * NN * D];
__device__ float g_f1[NN * D];
__device__ __nv_bfloat16 g_Bhi[5 * 256 * 512], g_Blo[5 * 256 * 512];

// ================= helpers =================
__device__ __forceinline__ uint32_t smem_u32(const void* p) {
    uint32_t a;
    asm("{ .reg .u64 t; cvta.to.shared.u64 t, %1; cvt.u32.u64 %0, t; }" : "=r"(a) : "l"(p));
    return a;
}
__device__ __forceinline__ void cp16(uint32_t dst, const void* src, bool valid) {
    int sz = valid ? 16 : 0;
    asm volatile("cp.async.cg.shared.global [%0], [%1], 16, %2;"
                 :: "r"(dst), "l"(__cvta_generic_to_global(src)), "r"(sz) : "memory");
}
#define CP_COMMIT() asm volatile("cp.async.commit_group;" ::: "memory")
#define CP_WAIT(n)  asm volatile("cp.async.wait_group %0;" :: "n"(n) : "memory")

__device__ __forceinline__ void add_bf2(float* a, uint32_t h, uint32_t l) {
    __nv_bfloat162 hh = *(__nv_bfloat162*)&h, ll = *(__nv_bfloat162*)&l;
    float2 fh = __bfloat1622float2(hh), fl = __bfloat1622float2(ll);
    a[0] += fh.x + fl.x;
    a[1] += fh.y + fl.y;
}
__device__ __forceinline__ uint32_t pack_hi(float v0, float v1, uint32_t& lo_out) {
    __nv_bfloat16 h0 = __float2bfloat16(v0);
    __nv_bfloat16 h1 = __float2bfloat16(v1);
    __nv_bfloat16 l0 = __float2bfloat16(v0 - __bfloat162float(h0));
    __nv_bfloat16 l1 = __float2bfloat16(v1 - __bfloat162float(h1));
    lo_out = (uint32_t)__bfloat16_as_ushort(l0) | ((uint32_t)__bfloat16_as_ushort(l1) << 16);
    return (uint32_t)__bfloat16_as_ushort(h0) | ((uint32_t)__bfloat16_as_ushort(h1) << 16);
}

// ================= CSR build =================
__global__ void zero_int_kernel() {
    int i = blockIdx.x * blockDim.x + threadIdx.x;
    if (i < NBKT) { g_deg[i] = 0; g_cur[i] = 0; }
}
__global__ void hist_kernel(const int* __restrict__ ei, const int* __restrict__ et) {
    int i = blockIdx.x * blockDim.x + threadIdx.x;
    if (i >= EE) return;
    int r = et[i];
    if (r >= NR) return;
    atomicAdd(&g_deg[r * NN + ei[i]], 1);
}
__global__ void scan_kernel() {
    __shared__ int ssum[1024];
    const int n = NBKT;
    const int tid = threadIdx.x;
    const int per = (n + 1023) / 1024;
    const int start = tid * per;
    int s = 0;
    for (int j = 0; j < per; j++) {
        int idx = start + j;
        if (idx < n) s += g_deg[idx];
    }
    ssum[tid] = s;
    __syncthreads();
    for (int off = 1; off < 1024; off <<= 1) {
        int v = (tid >= off) ? ssum[tid - off] : 0;
        __syncthreads();
        ssum[tid] += v;
        __syncthreads();
    }
    int run = (tid > 0) ? ssum[tid - 1] : 0;
    for (int j = 0; j < per; j++) {
        int idx = start + j;
        if (idx < n) { g_rowptr[idx] = run; run += g_deg[idx]; }
    }
    if (tid == 1023) g_rowptr[n] = run;
}
__global__ void scatter_kernel(const int* __restrict__ ei, const int* __restrict__ et) {
    int i = blockIdx.x * blockDim.x + threadIdx.x;
    if (i >= EE) return;
    int r = et[i];
    if (r >= NR) return;
    int b = r * NN + ei[i];
    int slot = g_rowptr[b] + atomicAdd(&g_cur[b], 1);
    g_adj[slot] = ei[EE + i];
}

// ================= conversions =================
__global__ void conv_x(const float* __restrict__ x) {
    int i = blockIdx.x * blockDim.x + threadIdx.x;
    if (i >= NN * D) return;
    float v = x[i];
    __nv_bfloat16 h = __float2bfloat16(v);
    g_xhi[i] = h;
    g_xlo[i] = __float2bfloat16(v - __bfloat162float(h));
}
__global__ void conv_B(const float* __restrict__ relW, const float* __restrict__ rootW,
                       const float* __restrict__ fc1w) {
    int i = blockIdx.x * blockDim.x + threadIdx.x;
    if (i >= 5 * 256 * 512) return;
    int g = i >> 17;
    int rem = i & 131071;
    int n = rem >> 9;
    int k = rem & 511;
    float v;
    if (g < 4) {
        v = (k < 256) ? relW[((size_t)g * 5 + g) * 65536 + (size_t)k * 256 + n]
                      : rootW[(size_t)g * 65536 + (size_t)(k - 256) * 256 + n];
    } else {
        v = fc1w[(size_t)k * 256 + n];
    }
    __nv_bfloat16 h = __float2bfloat16(v);
    g_Bhi[i] = h;
    g_Blo[i] = __float2bfloat16(v - __bfloat162float(h));
}

// ================= fused CSR aggregation: gather-mean -> hi/lo bf16 =================
// out rows [0..NN) : relA over inputs (inhiA, inloA); rows [NN..2NN): relB over (inhiB, inloB)
__global__ void agg_csr(const __nv_bfloat16* __restrict__ inhiA, const __nv_bfloat16* __restrict__ inloA,
                        const __nv_bfloat16* __restrict__ inhiB, const __nv_bfloat16* __restrict__ inloB,
                        int relA, int relB,
                        __nv_bfloat16* __restrict__ outhi, __nv_bfloat16* __restrict__ outlo) {
    int w = (blockIdx.x * blockDim.x + threadIdx.x) >> 5;
    int lane = threadIdx.x & 31;
    if (w >= 2 * NN) return;
    int half = (w >= NN);
    int node = w - half * NN;
    int rel = half ? relB : relA;
    const __nv_bfloat16* hi = half ? inhiB : inhiA;
    const __nv_bfloat16* lo = half ? inloB : inloA;
    int b = rel * NN + node;
    int beg = g_rowptr[b], end = g_rowptr[b + 1];
    float acc[8];
#pragma unroll
    for (int i = 0; i < 8; i++) acc[i] = 0.0f;
    for (int j = beg; j < end; j++) {
        int d = g_adj[j];
        uint4 vh = *(const uint4*)(hi + (size_t)d * D + lane * 8);
        uint4 vl = *(const uint4*)(lo + (size_t)d * D + lane * 8);
        add_bf2(acc + 0, vh.x, vl.x);
        add_bf2(acc + 2, vh.y, vl.y);
        add_bf2(acc + 4, vh.z, vl.z);
        add_bf2(acc + 6, vh.w, vl.w);
    }
    float inv = 1.0f / fmaxf((float)(end - beg), 1.0f);
    uint32_t oh[4], ol[4];
#pragma unroll
    for (int i = 0; i < 4; i++)
        oh[i] = pack_hi(acc[2 * i] * inv, acc[2 * i + 1] * inv, ol[i]);
    *(uint4*)(outhi + (size_t)w * D + lane * 8) = make_uint4(oh[0], oh[1], oh[2], oh[3]);
    *(uint4*)(outlo + (size_t)w * D + lane * 8) = make_uint4(ol[0], ol[1], ol[2], ol[3]);
}

// ================= WMMA bf16 split GEMM (two halves, per-half B/bias) =================
#define SMEM_BYTES 40960
#define NCHUNK 48

__global__ __launch_bounds__(256, 2)
void gemm_wmma(const __nv_bfloat16* __restrict__ A1hi, const __nv_bfloat16* __restrict__ A1lo,
               const __nv_bfloat16* __restrict__ A2hi, const __nv_bfloat16* __restrict__ A2lo,
               int a2_global,
               const __nv_bfloat16* __restrict__ B0hi, const __nv_bfloat16* __restrict__ B0lo,
               const float* __restrict__ bias0,
               const __nv_bfloat16* __restrict__ B1hi, const __nv_bfloat16* __restrict__ B1lo,
               const float* __restrict__ bias1,
               float* __restrict__ Cf, __nv_bfloat16* __restrict__ Chi, __nv_bfloat16* __restrict__ Clo) {
    extern __shared__ __align__(16) char smem[];
    const uint32_t sb = smem_u32(smem);
    const int tid = threadIdx.x;
    const int wid = tid >> 5;
    const int wm = wid >> 2;
    const int wn = wid & 3;
    const int half = blockIdx.x / NBLK;
    const int rl0 = (blockIdx.x % NBLK) * 128;
    const int grow0 = half * NN + rl0;
    const int col0 = blockIdx.y * 128;

    const __nv_bfloat16* Bhi = half ? B1hi : B0hi;
    const __nv_bfloat16* Blo = half ? B1lo : B0lo;
    const float* bias = half ? bias1 : bias0;

    wmma::fragment<wmma::accumulator, 16, 16, 16, float> acc[4][2];
#pragma unroll
    for (int mi = 0; mi < 4; mi++)
#pragma unroll
        for (int ni = 0; ni < 2; ni++) wmma::fill_fragment(acc[mi][ni], 0.0f);

    const int r_ld = tid >> 2;
    const int q_ld = tid & 3;

    auto issue = [&](int c) {
        const int b = c & 1;
        const int p = c >> 4;                  // 0: hi*Bhi, 1: hi*Blo, 2: lo*Bhi
        const int kglob = (c & 15) * 32;
        const bool isA1 = (kglob < 256);
        const __nv_bfloat16* Ap = isA1 ? ((p == 2) ? A1lo : A1hi)
                                       : ((p == 2) ? A2lo : A2hi);
        const int koff = kglob & 255;
        const __nv_bfloat16* Bp = (p == 1) ? Blo : Bhi;
        const uint32_t abase = sb + b * 20480;
        const uint32_t bbase = abase + 10240;
#pragma unroll
        for (int i = 0; i < 2; i++) {
            int r = r_ld + i * 64;
            int rl = rl0 + r;
            bool v = rl < NN;
            size_t arow;
            if (isA1) arow = (size_t)(v ? (grow0 + r) : 0);
            else      arow = (size_t)(v ? (a2_global ? (grow0 + r) : rl) : 0);
            cp16(abase + r * 80 + q_ld * 16, Ap + arow * 256 + koff + q_ld * 8, v);
            cp16(bbase + r * 80 + q_ld * 16, Bp + (size_t)(col0 + r) * 512 + kglob + q_ld * 8, true);
        }
    };

    issue(0);
    CP_COMMIT();

#pragma unroll 1
    for (int c = 0; c < NCHUNK; c++) {
        if (c < NCHUNK - 1) {
            issue(c + 1);
            CP_COMMIT();
            CP_WAIT(1);
        } else {
            CP_WAIT(0);
        }
        __syncthreads();

        const int b = c & 1;
        const __nv_bfloat16* As = (const __nv_bfloat16*)(smem + b * 20480);
        const __nv_bfloat16* Bs = (const __nv_bfloat16*)(smem + b * 20480 + 10240);
#pragma unroll
        for (int kk = 0; kk < 2; kk++) {
            wmma::fragment<wmma::matrix_a, 16, 16, 16, __nv_bfloat16, wmma::row_major> af[4];
            wmma::fragment<wmma::matrix_b, 16, 16, 16, __nv_bfloat16, wmma::col_major> bf[2];
#pragma unroll
            for (int mi = 0; mi < 4; mi++)
                wmma::load_matrix_sync(af[mi], As + (wm * 64 + mi * 16) * 40 + kk * 16, 40);
#pragma unroll
            for (int ni = 0; ni < 2; ni++)
                wmma::load_matrix_sync(bf[ni], Bs + (wn * 32 + ni * 16) * 40 + kk * 16, 40);
#pragma unroll
            for (int mi = 0; mi < 4; mi++)
#pragma unroll
                for (int ni = 0; ni < 2; ni++)
                    wmma::mma_sync(acc[mi][ni], af[mi], bf[ni], acc[mi][ni]);
        }
        __syncthreads();
    }

    // ---------------- epilogue ----------------
    float* Cs = (float*)smem;
    const int er = tid >> 2;
    const int ecq = tid & 3;
#pragma unroll 1
    for (int h = 0; h < 2; h++) {
        if (wm == h) {
#pragma unroll
            for (int mi = 0; mi < 4; mi++)
#pragma unroll
                for (int ni = 0; ni < 2; ni++)
                    wmma::store_matrix_sync(Cs + (mi * 16) * 132 + wn * 32 + ni * 16,
                                            acc[mi][ni], 132, wmma::mem_row_major);
        }
        __syncthreads();
        int rl = rl0 + h * 64 + er;
        if (rl < NN) {
            int gr = half * NN + rl;
            float v[32];
#pragma unroll
            for (int j = 0; j < 32; j++) {
                int ccol = ecq * 32 + j;
                v[j] = fmaxf(Cs[er * 132 + ccol] + __ldg(&bias[col0 + ccol]), 0.0f);
            }
            if (Cf) {
                float* crow = Cf + (size_t)gr * 256 + col0 + ecq * 32;
#pragma unroll
                for (int j = 0; j < 32; j += 4)
                    *(float4*)(crow + j) = make_float4(v[j], v[j + 1], v[j + 2], v[j + 3]);
            }
            if (Chi) {
                uint32_t ph[16], pl[16];
#pragma unroll
                for (int j = 0; j < 16; j++)
                    ph[j] = pack_hi(v[2 * j], v[2 * j + 1], pl[j]);
                uint32_t* hrow = (uint32_t*)(Chi + (size_t)gr * 256 + col0 + ecq * 32);
                uint32_t* lrow = (uint32_t*)(Clo + (size_t)gr * 256 + col0 + ecq * 32);
#pragma unroll
                for (int j = 0; j < 16; j += 4) {
                    *(uint4*)(hrow + j) = make_uint4(ph[j], ph[j + 1], ph[j + 2], ph[j + 3]);
                    *(uint4*)(lrow + j) = make_uint4(pl[j], pl[j + 1], pl[j + 2], pl[j + 3]);
                }
            }
        }
        __syncthreads();
    }
}

// ---------------- fc2 (256->16) + log_softmax ----------------
__global__ void fc2_lsm_kernel(const float* __restrict__ H,
                               const float* __restrict__ W,
                               const float* __restrict__ b,
                               float* __restrict__ out, int M) {
    __shared__ float sw[16 * 256];
    const int tid = threadIdx.x;
    for (int i = tid; i < 16 * 256; i += blockDim.x) {
        int n = i >> 8, k = i & 255;
        sw[i] = W[k * 16 + n];
    }
    __syncthreads();

    const int warp = tid >> 5;
    const int lane = tid & 31;
    const int row = blockIdx.x * 4 + warp;
    if (row >= M) return;

    const float* hrow = H + (size_t)row * D;
    float acc[16];
#pragma unroll
    for (int n = 0; n < 16; n++) acc[n] = 0.0f;
#pragma unroll
    for (int kk = 0; kk < 8; kk++) {
        int k = lane + 32 * kk;
        float hv = hrow[k];
#pragma unroll
        for (int n = 0; n < 16; n++) acc[n] = fmaf(hv, sw[n * 256 + k], acc[n]);
    }
#pragma unroll
    for (int n = 0; n < 16; n++) {
#pragma unroll
        for (int o = 16; o > 0; o >>= 1)
            acc[n] += __shfl_xor_sync(0xFFFFFFFFu, acc[n], o);
    }
    if (lane == 0) {
        float v[16];
        float mx = -1e30f;
#pragma unroll
        for (int n = 0; n < 16; n++) { v[n] = acc[n] + b[n]; mx = fmaxf(mx, v[n]); }
        float s = 0.0f;
#pragma unroll
        for (int n = 0; n < 16; n++) s += expf(v[n] - mx);
        float l = logf(s);
        float* orow = out + (size_t)row * 16;
#pragma unroll
        for (int n = 0; n < 16; n++) orow[n] = v[n] - mx - l;
    }
}

// ================= host =================
template <typename T>
static T* sym(const void* symbol) {
    void* p = nullptr;
    cudaGetSymbolAddress(&p, symbol);
    return (T*)p;
}

extern "C" void kernel_launch(void* const* d_in, const int* in_sizes, int n_in,
                              void* d_out, int out_size) {
    const float* x     = (const float*)d_in[0];
    const int*   ei    = (const int*)  d_in[1];
    const int*   et    = (const int*)  d_in[2];
    const float* relW  = (const float*)d_in[3];
    const float* rootW = (const float*)d_in[4];
    const float* bias  = (const float*)d_in[5];
    const float* fc1w  = (const float*)d_in[6];
    const float* fc1b  = (const float*)d_in[7];
    const float* fc2w  = (const float*)d_in[8];
    const float* fc2b  = (const float*)d_in[9];
    float* out = (float*)d_out;

    __nv_bfloat16* xhi = sym<__nv_bfloat16>(g_xhi);
    __nv_bfloat16* xlo = sym<__nv_bfloat16>(g_xlo);
    __nv_bfloat16* ahi = sym<__nv_bfloat16>(g_agghi);
    __nv_bfloat16* alo = sym<__nv_bfloat16>(g_agglo);
    __nv_bfloat16* hhi = sym<__nv_bfloat16>(g_hhi);
    __nv_bfloat16* hlo = sym<__nv_bfloat16>(g_hlo);
    __nv_bfloat16* ehi = sym<__nv_bfloat16>(g_ehi);
    __nv_bfloat16* elo = sym<__nv_bfloat16>(g_elo);
    __nv_bfloat16* Bhi = sym<__nv_bfloat16>(g_Bhi);
    __nv_bfloat16* Blo = sym<__nv_bfloat16>(g_Blo);
    float* f1 = sym<float>(g_f1);

    const size_t GB = 256 * 512;   // elems per gemm's B

    // CSR build
    zero_int_kernel<<<(NBKT + 255) / 256, 256>>>();
    hist_kernel<<<(EE + 255) / 256, 256>>>(ei, et);
    scan_kernel<<<1, 1024>>>();
    scatter_kernel<<<(EE + 255) / 256, 256>>>(ei, et);

    // conversions
    conv_B<<<(5 * 256 * 512 + 255) / 256, 256>>>(relW, rootW, fc1w);
    conv_x<<<(NN * D + 255) / 256, 256>>>(x);

    const dim3 ggrid2(2 * NBLK, 2);
    const dim3 ggrid1(NBLK, 2);
    const int aggBlocks = (2 * NN * 32 + 255) / 256;

    // stage A: convs {0,2} on x
    agg_csr<<<aggBlocks, 256>>>(xhi, xlo, xhi, xlo, 0, 2, ahi, alo);
    gemm_wmma<<<ggrid2, 256, SMEM_BYTES>>>(
        ahi, alo, xhi, xlo, /*a2_global=*/0,
        Bhi + 0 * GB, Blo + 0 * GB, bias + 0 * 256,
        Bhi + 2 * GB, Blo + 2 * GB, bias + 2 * 256,
        nullptr, hhi, hlo);

    // stage B: convs {1,3} on stage-A halves
    agg_csr<<<aggBlocks, 256>>>(hhi, hlo, hhi + (size_t)NN * D, hlo + (size_t)NN * D,
                                1, 3, ahi, alo);
    gemm_wmma<<<ggrid2, 256, SMEM_BYTES>>>(
        ahi, alo, hhi, hlo, /*a2_global=*/1,
        Bhi + 1 * GB, Blo + 1 * GB, bias + 1 * 256,
        Bhi + 3 * GB, Blo + 3 * GB, bias + 3 * 256,
        nullptr, ehi, elo);

    // fc1: [e0 | e1] -> f1 (f32)
    gemm_wmma<<<ggrid1, 256, SMEM_BYTES>>>(
        ehi, elo, ehi + (size_t)NN * D, elo + (size_t)NN * D, /*a2_global=*/0,
        Bhi + 4 * GB, Blo + 4 * GB, fc1b,
        Bhi + 4 * GB, Blo + 4 * GB, fc1b,
        f1, nullptr, nullptr);

    // fc2 + log_softmax
    fc2_lsm_kernel<<<(NN + 3) / 4, 128>>>(f1, fc2w, fc2b, out, NN);
}

// round 5
// speedup vs baseline: 2.1737x; 1.0994x over previous
#include <cuda_runtime.h>
#include <cuda_bf16.h>
#include <mma.h>
#include <cstdint>
#include <math.h>

using namespace nvcuda;

#define NN 20000
#define D  256
#define EE 500000
#define NR 4
#define NBKT (NR * NN)
#define NBLK 157   // row blocks per 20000-row half (128 rows each)

// ---------------- scratch (no allocations allowed) ----------------
__device__ int g_deg[NBKT];
__device__ int g_cur[NBKT];
__device__ int g_rowptr[NBKT + 1];
__device__ int g_adj[EE];

__device__ __nv_bfloat16 g_xhi[NN * D], g_xlo[NN * D];
__device__ __nv_bfloat16 g_agghi[2 * NN * D], g_agglo[2 * NN * D];
__device__ __nv_bfloat16 g_hhi[2 * NN * D], g_hlo[2 * NN * D];
__device__ __nv_bfloat16 g_ehi[2 * NN * D], g_elo[2 * NN * D];
__device__ float g_f1[NN * D];
__device__ __nv_bfloat16 g_Bhi[5 * 256 * 512], g_Blo[5 * 256 * 512];

// ================= helpers =================
__device__ __forceinline__ uint32_t smem_u32(const void* p) {
    uint32_t a;
    asm("{ .reg .u64 t; cvta.to.shared.u64 t, %1; cvt.u32.u64 %0, t; }" : "=r"(a) : "l"(p));
    return a;
}
__device__ __forceinline__ void cp16(uint32_t dst, const void* src, bool valid) {
    int sz = valid ? 16 : 0;   // src-size 0 -> zero-fill
    asm volatile("cp.async.cg.shared.global [%0], [%1], 16, %2;"
                 :: "r"(dst), "l"(__cvta_generic_to_global(src)), "r"(sz) : "memory");
}
#define CP_COMMIT() asm volatile("cp.async.commit_group;" ::: "memory")
#define CP_WAIT(n)  asm volatile("cp.async.wait_group %0;" :: "n"(n) : "memory")

__device__ __forceinline__ void add_bf2(float* a, uint32_t h, uint32_t l) {
    __nv_bfloat162 hh = *(__nv_bfloat162*)&h, ll = *(__nv_bfloat162*)&l;
    float2 fh = __bfloat1622float2(hh), fl = __bfloat1622float2(ll);
    a[0] += fh.x + fl.x;
    a[1] += fh.y + fl.y;
}
__device__ __forceinline__ uint32_t pack_hi(float v0, float v1, uint32_t& lo_out) {
    __nv_bfloat16 h0 = __float2bfloat16(v0);
    __nv_bfloat16 h1 = __float2bfloat16(v1);
    __nv_bfloat16 l0 = __float2bfloat16(v0 - __bfloat162float(h0));
    __nv_bfloat16 l1 = __float2bfloat16(v1 - __bfloat162float(h1));
    lo_out = (uint32_t)__bfloat16_as_ushort(l0) | ((uint32_t)__bfloat16_as_ushort(l1) << 16);
    return (uint32_t)__bfloat16_as_ushort(h0) | ((uint32_t)__bfloat16_as_ushort(h1) << 16);
}

// ================= CSR build =================
__global__ void zero_int_kernel() {
    int i = blockIdx.x * blockDim.x + threadIdx.x;
    if (i < NBKT) { g_deg[i] = 0; g_cur[i] = 0; }
}
__global__ void hist_kernel(const int* __restrict__ ei, const int* __restrict__ et) {
    int i = blockIdx.x * blockDim.x + threadIdx.x;
    if (i >= EE) return;
    int r = et[i];
    if (r >= NR) return;
    atomicAdd(&g_deg[r * NN + ei[i]], 1);
}
__global__ void scan_kernel() {
    __shared__ int ssum[1024];
    const int n = NBKT;
    const int tid = threadIdx.x;
    const int per = (n + 1023) / 1024;
    const int start = tid * per;
    int s = 0;
    for (int j = 0; j < per; j++) {
        int idx = start + j;
        if (idx < n) s += g_deg[idx];
    }
    ssum[tid] = s;
    __syncthreads();
    for (int off = 1; off < 1024; off <<= 1) {
        int v = (tid >= off) ? ssum[tid - off] : 0;
        __syncthreads();
        ssum[tid] += v;
        __syncthreads();
    }
    int run = (tid > 0) ? ssum[tid - 1] : 0;
    for (int j = 0; j < per; j++) {
        int idx = start + j;
        if (idx < n) { g_rowptr[idx] = run; run += g_deg[idx]; }
    }
    if (tid == 1023) g_rowptr[n] = run;
}
__global__ void scatter_kernel(const int* __restrict__ ei, const int* __restrict__ et) {
    int i = blockIdx.x * blockDim.x + threadIdx.x;
    if (i >= EE) return;
    int r = et[i];
    if (r >= NR) return;
    int b = r * NN + ei[i];
    int slot = g_rowptr[b] + atomicAdd(&g_cur[b], 1);
    g_adj[slot] = ei[EE + i];
}

// ================= conversions =================
__global__ void conv_x(const float* __restrict__ x) {
    int i = blockIdx.x * blockDim.x + threadIdx.x;
    if (i >= NN * D) return;
    float v = x[i];
    __nv_bfloat16 h = __float2bfloat16(v);
    g_xhi[i] = h;
    g_xlo[i] = __float2bfloat16(v - __bfloat162float(h));
}
__global__ void conv_B(const float* __restrict__ relW, const float* __restrict__ rootW,
                       const float* __restrict__ fc1w) {
    int i = blockIdx.x * blockDim.x + threadIdx.x;
    if (i >= 5 * 256 * 512) return;
    int g = i >> 17;
    int rem = i & 131071;
    int n = rem >> 9;
    int k = rem & 511;
    float v;
    if (g < 4) {
        v = (k < 256) ? relW[((size_t)g * 5 + g) * 65536 + (size_t)k * 256 + n]
                      : rootW[(size_t)g * 65536 + (size_t)(k - 256) * 256 + n];
    } else {
        v = fc1w[(size_t)k * 256 + n];
    }
    __nv_bfloat16 h = __float2bfloat16(v);
    g_Bhi[i] = h;
    g_Blo[i] = __float2bfloat16(v - __bfloat162float(h));
}

// ================= fused CSR aggregation =================
__global__ void agg_csr(const __nv_bfloat16* __restrict__ inhiA, const __nv_bfloat16* __restrict__ inloA,
                        const __nv_bfloat16* __restrict__ inhiB, const __nv_bfloat16* __restrict__ inloB,
                        int relA, int relB,
                        __nv_bfloat16* __restrict__ outhi, __nv_bfloat16* __restrict__ outlo) {
    int w = (blockIdx.x * blockDim.x + threadIdx.x) >> 5;
    int lane = threadIdx.x & 31;
    if (w >= 2 * NN) return;
    int half = (w >= NN);
    int node = w - half * NN;
    int rel = half ? relB : relA;
    const __nv_bfloat16* hi = half ? inhiB : inhiA;
    const __nv_bfloat16* lo = half ? inloB : inloA;
    int b = rel * NN + node;
    int beg = g_rowptr[b], end = g_rowptr[b + 1];
    float acc[8];
#pragma unroll
    for (int i = 0; i < 8; i++) acc[i] = 0.0f;
    for (int j = beg; j < end; j++) {
        int d = g_adj[j];
        uint4 vh = *(const uint4*)(hi + (size_t)d * D + lane * 8);
        uint4 vl = *(const uint4*)(lo + (size_t)d * D + lane * 8);
        add_bf2(acc + 0, vh.x, vl.x);
        add_bf2(acc + 2, vh.y, vl.y);
        add_bf2(acc + 4, vh.z, vl.z);
        add_bf2(acc + 6, vh.w, vl.w);
    }
    float inv = 1.0f / fmaxf((float)(end - beg), 1.0f);
    uint32_t oh[4], ol[4];
#pragma unroll
    for (int i = 0; i < 4; i++)
        oh[i] = pack_hi(acc[2 * i] * inv, acc[2 * i + 1] * inv, ol[i]);
    *(uint4*)(outhi + (size_t)w * D + lane * 8) = make_uint4(oh[0], oh[1], oh[2], oh[3]);
    *(uint4*)(outlo + (size_t)w * D + lane * 8) = make_uint4(ol[0], ol[1], ol[2], ol[3]);
}

// ================= WMMA bf16 split GEMM: KC=64, 3-stage pipeline =================
#define KC 64
#define ASTRIDE 72                      // bf16 elems per smem row (16B pad)
#define ATILE_B (128 * ASTRIDE * 2)     // 18432 bytes
#define STAGE_B (2 * ATILE_B)           // A + B = 36864 bytes
#define NSTAGE 3
#define SMEM_BYTES (NSTAGE * STAGE_B)   // 110592 bytes
#define NCHUNK 24

__global__ __launch_bounds__(256, 2)
void gemm_wmma(const __nv_bfloat16* __restrict__ A1hi, const __nv_bfloat16* __restrict__ A1lo,
               const __nv_bfloat16* __restrict__ A2hi, const __nv_bfloat16* __restrict__ A2lo,
               int a2_global,
               const __nv_bfloat16* __restrict__ B0hi, const __nv_bfloat16* __restrict__ B0lo,
               const float* __restrict__ bias0,
               const __nv_bfloat16* __restrict__ B1hi, const __nv_bfloat16* __restrict__ B1lo,
               const float* __restrict__ bias1,
               float* __restrict__ Cf, __nv_bfloat16* __restrict__ Chi, __nv_bfloat16* __restrict__ Clo) {
    extern __shared__ __align__(16) char smem[];
    const uint32_t sb = smem_u32(smem);
    const int tid = threadIdx.x;
    const int wid = tid >> 5;
    const int wm = wid >> 2;
    const int wn = wid & 3;
    const int half = blockIdx.x / NBLK;
    const int rl0 = (blockIdx.x % NBLK) * 128;
    const int grow0 = half * NN + rl0;
    const int col0 = blockIdx.y * 128;

    const __nv_bfloat16* Bhi = half ? B1hi : B0hi;
    const __nv_bfloat16* Blo = half ? B1lo : B0lo;
    const float* bias = half ? bias1 : bias0;

    wmma::fragment<wmma::accumulator, 16, 16, 16, float> acc[4][2];
#pragma unroll
    for (int mi = 0; mi < 4; mi++)
#pragma unroll
        for (int ni = 0; ni < 2; ni++) wmma::fill_fragment(acc[mi][ni], 0.0f);

    const int r_ld = tid >> 3;          // 0..31 (with +32k offsets -> 0..127)
    const int q_ld = tid & 7;           // 16B column chunk (0..7)

    auto issue = [&](int c) {
        const int st = c % NSTAGE;
        const int p = c >> 3;                  // 0: hi*Bhi, 1: hi*Blo, 2: lo*Bhi
        const int kglob = (c & 7) * KC;        // 0..448
        const bool isA1 = (kglob < 256);
        const __nv_bfloat16* Ap = isA1 ? ((p == 2) ? A1lo : A1hi)
                                       : ((p == 2) ? A2lo : A2hi);
        const int koff = kglob & 255;
        const __nv_bfloat16* Bp = (p == 1) ? Blo : Bhi;
        const uint32_t abase = sb + st * STAGE_B;
        const uint32_t bbase = abase + ATILE_B;
#pragma unroll
        for (int i = 0; i < 4; i++) {
            int r = r_ld + i * 32;
            int rl = rl0 + r;
            bool v = rl < NN;
            size_t arow;
            if (isA1) arow = (size_t)(v ? (grow0 + r) : 0);
            else      arow = (size_t)(v ? (a2_global ? (grow0 + r) : rl) : 0);
            cp16(abase + r * (ASTRIDE * 2) + q_ld * 16, Ap + arow * 256 + koff + q_ld * 8, v);
            cp16(bbase + r * (ASTRIDE * 2) + q_ld * 16,
                 Bp + (size_t)(col0 + r) * 512 + kglob + q_ld * 8, true);
        }
    };

    issue(0); CP_COMMIT();
    issue(1); CP_COMMIT();

#pragma unroll 1
    for (int c = 0; c < NCHUNK; c++) {
        CP_WAIT(1);            // stage c ready (per-thread), publish via barrier
        __syncthreads();       // also proves all warps left stage (c-1)%3
        if (c + 2 < NCHUNK) { issue(c + 2); CP_COMMIT(); }

        const int st = c % NSTAGE;
        const __nv_bfloat16* As = (const __nv_bfloat16*)(smem + st * STAGE_B);
        const __nv_bfloat16* Bs = (const __nv_bfloat16*)(smem + st * STAGE_B + ATILE_B);
#pragma unroll
        for (int kk = 0; kk < 4; kk++) {
            wmma::fragment<wmma::matrix_a, 16, 16, 16, __nv_bfloat16, wmma::row_major> af[4];
            wmma::fragment<wmma::matrix_b, 16, 16, 16, __nv_bfloat16, wmma::col_major> bf[2];
#pragma unroll
            for (int mi = 0; mi < 4; mi++)
                wmma::load_matrix_sync(af[mi], As + (wm * 64 + mi * 16) * ASTRIDE + kk * 16, ASTRIDE);
#pragma unroll
            for (int ni = 0; ni < 2; ni++)
                wmma::load_matrix_sync(bf[ni], Bs + (wn * 32 + ni * 16) * ASTRIDE + kk * 16, ASTRIDE);
#pragma unroll
            for (int mi = 0; mi < 4; mi++)
#pragma unroll
                for (int ni = 0; ni < 2; ni++)
                    wmma::mma_sync(acc[mi][ni], af[mi], bf[ni], acc[mi][ni]);
        }
    }
    __syncthreads();   // all compute done before smem reuse

    // ---------------- epilogue: two 64-row halves through smem ----------------
    float* Cs = (float*)smem;
    const int er = tid >> 2;
    const int ecq = tid & 3;
#pragma unroll 1
    for (int h = 0; h < 2; h++) {
        if (wm == h) {
#pragma unroll
            for (int mi = 0; mi < 4; mi++)
#pragma unroll
                for (int ni = 0; ni < 2; ni++)
                    wmma::store_matrix_sync(Cs + (mi * 16) * 132 + wn * 32 + ni * 16,
                                            acc[mi][ni], 132, wmma::mem_row_major);
        }
        __syncthreads();
        int rl = rl0 + h * 64 + er;
        if (rl < NN) {
            int gr = half * NN + rl;
            float v[32];
#pragma unroll
            for (int j = 0; j < 32; j++) {
                int ccol = ecq * 32 + j;
                v[j] = fmaxf(Cs[er * 132 + ccol] + __ldg(&bias[col0 + ccol]), 0.0f);
            }
            if (Cf) {
                float* crow = Cf + (size_t)gr * 256 + col0 + ecq * 32;
#pragma unroll
                for (int j = 0; j < 32; j += 4)
                    *(float4*)(crow + j) = make_float4(v[j], v[j + 1], v[j + 2], v[j + 3]);
            }
            if (Chi) {
                uint32_t ph[16], pl[16];
#pragma unroll
                for (int j = 0; j < 16; j++)
                    ph[j] = pack_hi(v[2 * j], v[2 * j + 1], pl[j]);
                uint32_t* hrow = (uint32_t*)(Chi + (size_t)gr * 256 + col0 + ecq * 32);
                uint32_t* lrow = (uint32_t*)(Clo + (size_t)gr * 256 + col0 + ecq * 32);
#pragma unroll
                for (int j = 0; j < 16; j += 4) {
                    *(uint4*)(hrow + j) = make_uint4(ph[j], ph[j + 1], ph[j + 2], ph[j + 3]);
                    *(uint4*)(lrow + j) = make_uint4(pl[j], pl[j + 1], pl[j + 2], pl[j + 3]);
                }
            }
        }
        __syncthreads();
    }
}

// ---------------- fc2 (256->16) + log_softmax ----------------
__global__ void fc2_lsm_kernel(const float* __restrict__ H,
                               const float* __restrict__ W,
                               const float* __restrict__ b,
                               float* __restrict__ out, int M) {
    __shared__ float sw[16 * 256];
    const int tid = threadIdx.x;
    for (int i = tid; i < 16 * 256; i += blockDim.x) {
        int n = i >> 8, k = i & 255;
        sw[i] = W[k * 16 + n];
    }
    __syncthreads();

    const int warp = tid >> 5;
    const int lane = tid & 31;
    const int row = blockIdx.x * 4 + warp;
    if (row >= M) return;

    const float* hrow = H + (size_t)row * D;
    float acc[16];
#pragma unroll
    for (int n = 0; n < 16; n++) acc[n] = 0.0f;
#pragma unroll
    for (int kk = 0; kk < 8; kk++) {
        int k = lane + 32 * kk;
        float hv = hrow[k];
#pragma unroll
        for (int n = 0; n < 16; n++) acc[n] = fmaf(hv, sw[n * 256 + k], acc[n]);
    }
#pragma unroll
    for (int n = 0; n < 16; n++) {
#pragma unroll
        for (int o = 16; o > 0; o >>= 1)
            acc[n] += __shfl_xor_sync(0xFFFFFFFFu, acc[n], o);
    }
    if (lane == 0) {
        float v[16];
        float mx = -1e30f;
#pragma unroll
        for (int n = 0; n < 16; n++) { v[n] = acc[n] + b[n]; mx = fmaxf(mx, v[n]); }
        float s = 0.0f;
#pragma unroll
        for (int n = 0; n < 16; n++) s += expf(v[n] - mx);
        float l = logf(s);
        float* orow = out + (size_t)row * 16;
#pragma unroll
        for (int n = 0; n < 16; n++) orow[n] = v[n] - mx - l;
    }
}

// ================= host =================
template <typename T>
static T* sym(const void* symbol) {
    void* p = nullptr;
    cudaGetSymbolAddress(&p, symbol);
    return (T*)p;
}

extern "C" void kernel_launch(void* const* d_in, const int* in_sizes, int n_in,
                              void* d_out, int out_size) {
    const float* x     = (const float*)d_in[0];
    const int*   ei    = (const int*)  d_in[1];
    const int*   et    = (const int*)  d_in[2];
    const float* relW  = (const float*)d_in[3];
    const float* rootW = (const float*)d_in[4];
    const float* bias  = (const float*)d_in[5];
    const float* fc1w  = (const float*)d_in[6];
    const float* fc1b  = (const float*)d_in[7];
    const float* fc2w  = (const float*)d_in[8];
    const float* fc2b  = (const float*)d_in[9];
    float* out = (float*)d_out;

    __nv_bfloat16* xhi = sym<__nv_bfloat16>(g_xhi);
    __nv_bfloat16* xlo = sym<__nv_bfloat16>(g_xlo);
    __nv_bfloat16* ahi = sym<__nv_bfloat16>(g_agghi);
    __nv_bfloat16* alo = sym<__nv_bfloat16>(g_agglo);
    __nv_bfloat16* hhi = sym<__nv_bfloat16>(g_hhi);
    __nv_bfloat16* hlo = sym<__nv_bfloat16>(g_hlo);
    __nv_bfloat16* ehi = sym<__nv_bfloat16>(g_ehi);
    __nv_bfloat16* elo = sym<__nv_bfloat16>(g_elo);
    __nv_bfloat16* Bhi = sym<__nv_bfloat16>(g_Bhi);
    __nv_bfloat16* Blo = sym<__nv_bfloat16>(g_Blo);
    float* f1 = sym<float>(g_f1);

    cudaFuncSetAttribute(gemm_wmma, cudaFuncAttributeMaxDynamicSharedMemorySize, SMEM_BYTES);

    const size_t GB = 256 * 512;

    // CSR build
    zero_int_kernel<<<(NBKT + 255) / 256, 256>>>();
    hist_kernel<<<(EE + 255) / 256, 256>>>(ei, et);
    scan_kernel<<<1, 1024>>>();
    scatter_kernel<<<(EE + 255) / 256, 256>>>(ei, et);

    // conversions
    conv_B<<<(5 * 256 * 512 + 255) / 256, 256>>>(relW, rootW, fc1w);
    conv_x<<<(NN * D + 255) / 256, 256>>>(x);

    const dim3 ggrid2(2 * NBLK, 2);
    const dim3 ggrid1(NBLK, 2);
    const int aggBlocks = (2 * NN * 32 + 255) / 256;

    // stage A: convs {0,2} on x
    agg_csr<<<aggBlocks, 256>>>(xhi, xlo, xhi, xlo, 0, 2, ahi, alo);
    gemm_wmma<<<ggrid2, 256, SMEM_BYTES>>>(
        ahi, alo, xhi, xlo, /*a2_global=*/0,
        Bhi + 0 * GB, Blo + 0 * GB, bias + 0 * 256,
        Bhi + 2 * GB, Blo + 2 * GB, bias + 2 * 256,
        nullptr, hhi, hlo);

    // stage B: convs {1,3} on stage-A halves
    agg_csr<<<aggBlocks, 256>>>(hhi, hlo, hhi + (size_t)NN * D, hlo + (size_t)NN * D,
                                1, 3, ahi, alo);
    gemm_wmma<<<ggrid2, 256, SMEM_BYTES>>>(
        ahi, alo, hhi, hlo, /*a2_global=*/1,
        Bhi + 1 * GB, Blo + 1 * GB, bias + 1 * 256,
        Bhi + 3 * GB, Blo + 3 * GB, bias + 3 * 256,
        nullptr, ehi, elo);

    // fc1: [e0 | e1] -> f1 (f32)
    gemm_wmma<<<ggrid1, 256, SMEM_BYTES>>>(
        ehi, elo, ehi + (size_t)NN * D, elo + (size_t)NN * D, /*a2_global=*/0,
        Bhi + 4 * GB, Blo + 4 * GB, fc1b,
        Bhi + 4 * GB, Blo + 4 * GB, fc1b,
        f1, nullptr, nullptr);

    // fc2 + log_softmax
    fc2_lsm_kernel<<<(NN + 3) / 4, 128>>>(f1, fc2w, fc2b, out, NN);
}

// round 6
// speedup vs baseline: 2.7619x; 1.2706x over previous
#include <cuda_runtime.h>
#include <cuda_bf16.h>
#include <cstdint>
#include <math.h>

#define NN 20000
#define D  256
#define EE 500000
#define NR 4
#define NBKT (NR * NN)
#define NBLK 157                 // 128-row blocks per 20000-row half
#define TILE_ELEMS 8192          // 128 rows x 64 k bf16
#define TILE_BYTES 16384
#define ATILES (NBLK * 4)        // tiles per 256-wide half-array (628)
#define HALF_OFF ((size_t)ATILES * TILE_ELEMS)

// ---------------- scratch (no allocations allowed) ----------------
__device__ int g_deg[NBKT];
__device__ int g_cur[NBKT];
__device__ int g_rowptr[NBKT + 1];
__device__ int g_adj[EE];

__device__ __nv_bfloat16 g_xhi[ATILES * TILE_ELEMS], g_xlo[ATILES * TILE_ELEMS];
__device__ __nv_bfloat16 g_agghi[2 * ATILES * TILE_ELEMS], g_agglo[2 * ATILES * TILE_ELEMS];
__device__ __nv_bfloat16 g_hhi[2 * ATILES * TILE_ELEMS], g_hlo[2 * ATILES * TILE_ELEMS];
__device__ __nv_bfloat16 g_ehi[2 * ATILES * TILE_ELEMS], g_elo[2 * ATILES * TILE_ELEMS];
__device__ float g_f1[NN * D];
// B: [gemm 5][colblock 2][kc 8][tile]
__device__ __nv_bfloat16 g_Bhi[5 * 16 * TILE_ELEMS], g_Blo[5 * 16 * TILE_ELEMS];

// ================= helpers =================
__device__ __forceinline__ uint32_t smem_u32(const void* p) {
    uint32_t a;
    asm("{ .reg .u64 t; cvta.to.shared.u64 t, %1; cvt.u32.u64 %0, t; }" : "=r"(a) : "l"(p));
    return a;
}
// byte offset of (row r, col k) inside a 128x64 bf16 tile with XOR-swizzled 128B rows
__device__ __forceinline__ uint32_t tileoff_b(int r, int k) {
    return (uint32_t)(r * 128 + ((((k >> 3) ^ r) & 7) << 4) + ((k & 7) << 1));
}
#define MBAR_INIT(addr, cnt) \
    asm volatile("mbarrier.init.shared.b64 [%0], %1;" :: "r"(addr), "r"(cnt) : "memory")
#define MBAR_EXPECT_TX(addr, bytes) \
    asm volatile("mbarrier.arrive.expect_tx.shared.b64 _, [%0], %1;" :: "r"(addr), "r"(bytes) : "memory")
#define MBAR_WAIT(addr, parity) do {                                              \
    uint32_t _m = (addr); uint32_t _p = (parity); uint32_t _done;                 \
    asm volatile("{\n\t.reg .pred p;\n\t"                                         \
        "mbarrier.try_wait.parity.acquire.cta.shared::cta.b64 p, [%1], %2;\n\t"   \
        "selp.b32 %0, 1, 0, p;\n\t}"                                              \
        : "=r"(_done) : "r"(_m), "r"(_p) : "memory");                             \
    if (!_done) {                                                                 \
        asm volatile("{\n\t.reg .pred P1;\n\t"                                    \
            "WL_%=:\n\t"                                                          \
            "mbarrier.try_wait.parity.acquire.cta.shared::cta.b64 P1, [%0], %1, 0x989680;\n\t" \
            "@P1 bra.uni WD_%=;\n\t"                                              \
            "bra.uni WL_%=;\n\t"                                                  \
            "WD_%=:\n\t}" :: "r"(_m), "r"(_p) : "memory");                        \
    }                                                                             \
} while (0)
__device__ __forceinline__ void bulk_g2s(uint32_t dst, const void* src, uint32_t bytes, uint32_t mbar) {
    asm volatile("cp.async.bulk.shared::cluster.global.mbarrier::complete_tx::bytes [%0], [%1], %2, [%3];"
                 :: "r"(dst), "l"(__cvta_generic_to_global(src)), "r"(bytes), "r"(mbar) : "memory");
}
__device__ __forceinline__ void ldsm4(uint32_t* r, uint32_t addr) {
    asm volatile("ldmatrix.sync.aligned.m8n8.x4.shared.b16 {%0,%1,%2,%3}, [%4];"
                 : "=r"(r[0]), "=r"(r[1]), "=r"(r[2]), "=r"(r[3]) : "r"(addr));
}
__device__ __forceinline__ void mma16816(float* c, const uint32_t* a, uint32_t b0, uint32_t b1) {
    asm volatile("mma.sync.aligned.m16n8k16.row.col.f32.bf16.bf16.f32 "
                 "{%0,%1,%2,%3}, {%4,%5,%6,%7}, {%8,%9}, {%0,%1,%2,%3};"
                 : "+f"(c[0]), "+f"(c[1]), "+f"(c[2]), "+f"(c[3])
                 : "r"(a[0]), "r"(a[1]), "r"(a[2]), "r"(a[3]), "r"(b0), "r"(b1));
}
__device__ __forceinline__ void add_bf2(float* a, uint32_t h, uint32_t l) {
    __nv_bfloat162 hh = *(__nv_bfloat162*)&h, ll = *(__nv_bfloat162*)&l;
    float2 fh = __bfloat1622float2(hh), fl = __bfloat1622float2(ll);
    a[0] += fh.x + fl.x;
    a[1] += fh.y + fl.y;
}
__device__ __forceinline__ uint32_t pack_hi(float v0, float v1, uint32_t& lo_out) {
    __nv_bfloat16 h0 = __float2bfloat16(v0);
    __nv_bfloat16 h1 = __float2bfloat16(v1);
    __nv_bfloat16 l0 = __float2bfloat16(v0 - __bfloat162float(h0));
    __nv_bfloat16 l1 = __float2bfloat16(v1 - __bfloat162float(h1));
    lo_out = (uint32_t)__bfloat16_as_ushort(l0) | ((uint32_t)__bfloat16_as_ushort(l1) << 16);
    return (uint32_t)__bfloat16_as_ushort(h0) | ((uint32_t)__bfloat16_as_ushort(h1) << 16);
}

// ================= CSR build =================
__global__ void zero_int_kernel() {
    int i = blockIdx.x * blockDim.x + threadIdx.x;
    if (i < NBKT) { g_deg[i] = 0; g_cur[i] = 0; }
}
__global__ void hist_kernel(const int* __restrict__ ei, const int* __restrict__ et) {
    int i = blockIdx.x * blockDim.x + threadIdx.x;
    if (i >= EE) return;
    int r = et[i];
    if (r >= NR) return;
    atomicAdd(&g_deg[r * NN + ei[i]], 1);
}
__global__ void scan_kernel() {
    __shared__ int ssum[1024];
    const int n = NBKT;
    const int tid = threadIdx.x;
    const int per = (n + 1023) / 1024;
    const int start = tid * per;
    int s = 0;
    for (int j = 0; j < per; j++) {
        int idx = start + j;
        if (idx < n) s += g_deg[idx];
    }
    ssum[tid] = s;
    __syncthreads();
    for (int off = 1; off < 1024; off <<= 1) {
        int v = (tid >= off) ? ssum[tid - off] : 0;
        __syncthreads();
        ssum[tid] += v;
        __syncthreads();
    }
    int run = (tid > 0) ? ssum[tid - 1] : 0;
    for (int j = 0; j < per; j++) {
        int idx = start + j;
        if (idx < n) { g_rowptr[idx] = run; run += g_deg[idx]; }
    }
    if (tid == 1023) g_rowptr[n] = run;
}
__global__ void scatter_kernel(const int* __restrict__ ei, const int* __restrict__ et) {
    int i = blockIdx.x * blockDim.x + threadIdx.x;
    if (i >= EE) return;
    int r = et[i];
    if (r >= NR) return;
    int b = r * NN + ei[i];
    int slot = g_rowptr[b] + atomicAdd(&g_cur[b], 1);
    g_adj[slot] = ei[EE + i];
}

// ================= conversions (write tiled+swizzled) =================
__global__ void conv_x(const float* __restrict__ x) {
    int gid = blockIdx.x * blockDim.x + threadIdx.x;  // one 16B chunk each
    if (gid >= NN * 32) return;
    int row = gid >> 5, cc = gid & 31;
    int kc = cc >> 3, c = cc & 7;
    int r = row & 127;
    const float* src = x + (size_t)row * 256 + cc * 8;
    float4 f0 = *(const float4*)src;
    float4 f1 = *(const float4*)(src + 4);
    uint4 hi, lo;
    hi.x = pack_hi(f0.x, f0.y, lo.x);
    hi.y = pack_hi(f0.z, f0.w, lo.y);
    hi.z = pack_hi(f1.x, f1.y, lo.z);
    hi.w = pack_hi(f1.z, f1.w, lo.w);
    size_t off = (size_t)((row >> 7) * 4 + kc) * TILE_BYTES + r * 128 + (((c ^ r) & 7) << 4);
    *(uint4*)((char*)g_xhi + off) = hi;
    *(uint4*)((char*)g_xlo + off) = lo;
}
__global__ void conv_B(const float* __restrict__ relW, const float* __restrict__ rootW,
                       const float* __restrict__ fc1w) {
    int gid = blockIdx.x * blockDim.x + threadIdx.x;  // one 16B chunk each
    if (gid >= 5 * 16 * 1024) return;                 // 81920 chunks
    int g = gid >> 14;
    int r1 = gid & 16383;
    int cb = r1 >> 13;
    int r2 = r1 & 8191;
    int kc = r2 >> 10;
    int r3 = r2 & 1023;
    int row = r3 >> 3;       // n within tile
    int c = r3 & 7;
    int n = cb * 128 + row;
    int kbase = kc * 64 + c * 8;
    float v[8];
#pragma unroll
    for (int j = 0; j < 8; j++) {
        int k = kbase + j;
        if (g < 4)
            v[j] = (k < 256) ? relW[(((size_t)g * 5 + g) * 256 + k) * 256 + n]
                             : rootW[((size_t)g * 256 + (k - 256)) * 256 + n];
        else
            v[j] = fc1w[(size_t)k * 256 + n];
    }
    uint4 hi, lo;
    hi.x = pack_hi(v[0], v[1], lo.x);
    hi.y = pack_hi(v[2], v[3], lo.y);
    hi.z = pack_hi(v[4], v[5], lo.z);
    hi.w = pack_hi(v[6], v[7], lo.w);
    size_t off = (size_t)(g * 16 + cb * 8 + kc) * TILE_BYTES + row * 128 + (((c ^ row) & 7) << 4);
    *(uint4*)((char*)g_Bhi + off) = hi;
    *(uint4*)((char*)g_Blo + off) = lo;
}

// ================= fused CSR aggregation (tiled in/out) =================
__global__ void agg_csr(const __nv_bfloat16* __restrict__ inhiA, const __nv_bfloat16* __restrict__ inloA,
                        const __nv_bfloat16* __restrict__ inhiB, const __nv_bfloat16* __restrict__ inloB,
                        int relA, int relB,
                        __nv_bfloat16* __restrict__ outhi, __nv_bfloat16* __restrict__ outlo) {
    int w = (blockIdx.x * blockDim.x + threadIdx.x) >> 5;
    int lane = threadIdx.x & 31;
    if (w >= 2 * NN) return;
    int half = (w >= NN);
    int node = w - half * NN;
    int rel = half ? relB : relA;
    const char* hib = (const char*)(half ? inhiB : inhiA);
    const char* lob = (const char*)(half ? inloB : inloA);
    int b = rel * NN + node;
    int beg = g_rowptr[b], end = g_rowptr[b + 1];
    const int kc = lane >> 3, cc = lane & 7;
    float acc[8];
#pragma unroll
    for (int i = 0; i < 8; i++) acc[i] = 0.0f;
    for (int j = beg; j < end; j++) {
        int d = g_adj[j];
        int r = d & 127;
        size_t tb = (size_t)((d >> 7) * 4 + kc) * TILE_BYTES + r * 128 + (((cc ^ r) & 7) << 4);
        uint4 vh = *(const uint4*)(hib + tb);
        uint4 vl = *(const uint4*)(lob + tb);
        add_bf2(acc + 0, vh.x, vl.x);
        add_bf2(acc + 2, vh.y, vl.y);
        add_bf2(acc + 4, vh.z, vl.z);
        add_bf2(acc + 6, vh.w, vl.w);
    }
    float inv = 1.0f / fmaxf((float)(end - beg), 1.0f);
    uint4 oh, ol;
    oh.x = pack_hi(acc[0] * inv, acc[1] * inv, ol.x);
    oh.y = pack_hi(acc[2] * inv, acc[3] * inv, ol.y);
    oh.z = pack_hi(acc[4] * inv, acc[5] * inv, ol.z);
    oh.w = pack_hi(acc[6] * inv, acc[7] * inv, ol.w);
    int r = node & 127;
    size_t ob = (size_t)((half * NBLK + (node >> 7)) * 4 + kc) * TILE_BYTES
              + r * 128 + (((cc ^ r) & 7) << 4);
    *(uint4*)((char*)outhi + ob) = oh;
    *(uint4*)((char*)outlo + ob) = ol;
}

// ================= bulk-copy MMA GEMM =================
// C[.,256] = relu( [A1|A2] @ Bt^T + bias ), fp32 via bf16 hi/lo split.
// 8 k-chunks of 64; per chunk one 64KB bulk load (Ahi,Alo,Bhi,Blo), 3 MMA phases.
#define NSTAGE 3
#define STAGE_BYTES 65536
#define SMEM_BYTES (NSTAGE * STAGE_BYTES)   // 196608

__global__ __launch_bounds__(256, 1)
void gemm_mma(const __nv_bfloat16* __restrict__ A1hi, const __nv_bfloat16* __restrict__ A1lo,
              const __nv_bfloat16* __restrict__ A2hi, const __nv_bfloat16* __restrict__ A2lo,
              int a2_global,
              const __nv_bfloat16* __restrict__ B0hi, const __nv_bfloat16* __restrict__ B0lo,
              const float* __restrict__ bias0,
              const __nv_bfloat16* __restrict__ B1hi, const __nv_bfloat16* __restrict__ B1lo,
              const float* __restrict__ bias1,
              float* __restrict__ Cf, __nv_bfloat16* __restrict__ Chi, __nv_bfloat16* __restrict__ Clo) {
    extern __shared__ __align__(16) char smem[];
    __shared__ __align__(8) uint64_t mbar[NSTAGE];
    const uint32_t sb = smem_u32(smem);
    const uint32_t sbar = smem_u32(mbar);
    const int tid = threadIdx.x;
    const int lane = tid & 31;
    const int wid = tid >> 5;
    const int wm = wid >> 2, wn = wid & 3;
    const int gblk = blockIdx.x;
    const int half = (gblk >= NBLK) ? 1 : 0;
    const int lblk = gblk - half * NBLK;
    const int cb = blockIdx.y;
    const int a2blk = a2_global ? gblk : lblk;
    const __nv_bfloat16* Bhi = half ? B1hi : B0hi;
    const __nv_bfloat16* Blo = half ? B1lo : B0lo;
    const float* bias = half ? bias1 : bias0;

    if (tid == 0) {
#pragma unroll
        for (int s = 0; s < NSTAGE; s++) MBAR_INIT(sbar + s * 8, 1);
    }
    __syncthreads();

    auto issue = [&](int c) {
        const int s = c % NSTAGE;
        const uint32_t bar = sbar + s * 8;
        const uint32_t dst = sb + s * STAGE_BYTES;
        const __nv_bfloat16 *ah, *al;
        if (c < 4) {
            ah = A1hi + (size_t)(gblk * 4 + c) * TILE_ELEMS;
            al = A1lo + (size_t)(gblk * 4 + c) * TILE_ELEMS;
        } else {
            ah = A2hi + (size_t)(a2blk * 4 + c - 4) * TILE_ELEMS;
            al = A2lo + (size_t)(a2blk * 4 + c - 4) * TILE_ELEMS;
        }
        const __nv_bfloat16* bh = Bhi + (size_t)(cb * 8 + c) * TILE_ELEMS;
        const __nv_bfloat16* bl = Blo + (size_t)(cb * 8 + c) * TILE_ELEMS;
        MBAR_EXPECT_TX(bar, STAGE_BYTES);
        bulk_g2s(dst,         ah, TILE_BYTES, bar);
        bulk_g2s(dst + 16384, al, TILE_BYTES, bar);
        bulk_g2s(dst + 32768, bh, TILE_BYTES, bar);
        bulk_g2s(dst + 49152, bl, TILE_BYTES, bar);
    };

    if (tid == 0) { issue(0); issue(1); issue(2); }

    float acc[4][4][4];
#pragma unroll
    for (int a = 0; a < 4; a++)
#pragma unroll
        for (int b = 0; b < 4; b++)
#pragma unroll
            for (int c = 0; c < 4; c++) acc[a][b][c] = 0.0f;

    const int rA0 = wm * 64 + (lane & 15);
    const int rB0 = wn * 32 + (lane & 15);
    const int ksub = (lane >> 4) << 3;

#pragma unroll 1
    for (int c = 0; c < 8; c++) {
        MBAR_WAIT(sbar + (c % NSTAGE) * 8, (c / NSTAGE) & 1);
        const uint32_t st = sb + (c % NSTAGE) * STAGE_BYTES;
#pragma unroll
        for (int kk = 0; kk < 4; kk++) {
            const int kof = kk * 16 + ksub;
            uint32_t ahf[4][4], alf[4][4], bhf[2][4], blf[2][4];
#pragma unroll
            for (int mi = 0; mi < 4; mi++) {
                ldsm4(ahf[mi], st + tileoff_b(rA0 + mi * 16, kof));
                ldsm4(alf[mi], st + 16384 + tileoff_b(rA0 + mi * 16, kof));
            }
#pragma unroll
            for (int np = 0; np < 2; np++) {
                ldsm4(bhf[np], st + 32768 + tileoff_b(rB0 + np * 16, kof));
                ldsm4(blf[np], st + 49152 + tileoff_b(rB0 + np * 16, kof));
            }
#pragma unroll
            for (int mi = 0; mi < 4; mi++)
#pragma unroll
                for (int np = 0; np < 2; np++) {
                    mma16816(acc[mi][np * 2 + 0], ahf[mi], bhf[np][0], bhf[np][2]);
                    mma16816(acc[mi][np * 2 + 1], ahf[mi], bhf[np][1], bhf[np][3]);
                    mma16816(acc[mi][np * 2 + 0], ahf[mi], blf[np][0], blf[np][2]);
                    mma16816(acc[mi][np * 2 + 1], ahf[mi], blf[np][1], blf[np][3]);
                    mma16816(acc[mi][np * 2 + 0], alf[mi], bhf[np][0], bhf[np][2]);
                    mma16816(acc[mi][np * 2 + 1], alf[mi], bhf[np][1], bhf[np][3]);
                }
        }
        __syncthreads();                       // all warps done with stage c%3
        if (tid == 0 && c + NSTAGE < 8) issue(c + NSTAGE);
    }

    // ---------------- epilogue: direct global stores ----------------
    const int tq = lane & 3, trr = lane >> 2;
    float bv[4][2];
#pragma unroll
    for (int ni = 0; ni < 4; ni++) {
        int colg = cb * 128 + wn * 32 + ni * 8 + tq * 2;
        bv[ni][0] = __ldg(&bias[colg]);
        bv[ni][1] = __ldg(&bias[colg + 1]);
    }
#pragma unroll
    for (int mi = 0; mi < 4; mi++) {
#pragma unroll
        for (int hr = 0; hr < 2; hr++) {
            const int r = wm * 64 + mi * 16 + trr + hr * 8;
            const int rl = lblk * 128 + r;
            if (rl >= NN) continue;
#pragma unroll
            for (int ni = 0; ni < 4; ni++) {
                float v0 = fmaxf(acc[mi][ni][hr * 2 + 0] + bv[ni][0], 0.0f);
                float v1 = fmaxf(acc[mi][ni][hr * 2 + 1] + bv[ni][1], 0.0f);
                const int colg = cb * 128 + wn * 32 + ni * 8 + tq * 2;
                if (Cf)
                    *(float2*)(Cf + (size_t)rl * 256 + colg) = make_float2(v0, v1);
                if (Chi) {
                    uint32_t lo32;
                    uint32_t hi32 = pack_hi(v0, v1, lo32);
                    const int kc = colg >> 6, kl = colg & 63;
                    const size_t off = (size_t)(gblk * 4 + kc) * TILE_BYTES + tileoff_b(r, kl);
                    *(uint32_t*)((char*)Chi + off) = hi32;
                    *(uint32_t*)((char*)Clo + off) = lo32;
                }
            }
        }
    }
}

// ---------------- fc2 (256->16) + log_softmax ----------------
__global__ void fc2_lsm_kernel(const float* __restrict__ H,
                               const float* __restrict__ W,
                               const float* __restrict__ b,
                               float* __restrict__ out, int M) {
    __shared__ float sw[16 * 256];
    const int tid = threadIdx.x;
    for (int i = tid; i < 16 * 256; i += blockDim.x) {
        int n = i >> 8, k = i & 255;
        sw[i] = W[k * 16 + n];
    }
    __syncthreads();

    const int warp = tid >> 5;
    const int lane = tid & 31;
    const int row = blockIdx.x * 4 + warp;
    if (row >= M) return;

    const float* hrow = H + (size_t)row * D;
    float acc[16];
#pragma unroll
    for (int n = 0; n < 16; n++) acc[n] = 0.0f;
#pragma unroll
    for (int kk = 0; kk < 8; kk++) {
        int k = lane + 32 * kk;
        float hv = hrow[k];
#pragma unroll
        for (int n = 0; n < 16; n++) acc[n] = fmaf(hv, sw[n * 256 + k], acc[n]);
    }
#pragma unroll
    for (int n = 0; n < 16; n++) {
#pragma unroll
        for (int o = 16; o > 0; o >>= 1)
            acc[n] += __shfl_xor_sync(0xFFFFFFFFu, acc[n], o);
    }
    if (lane == 0) {
        float v[16];
        float mx = -1e30f;
#pragma unroll
        for (int n = 0; n < 16; n++) { v[n] = acc[n] + b[n]; mx = fmaxf(mx, v[n]); }
        float s = 0.0f;
#pragma unroll
        for (int n = 0; n < 16; n++) s += expf(v[n] - mx);
        float l = logf(s);
        float* orow = out + (size_t)row * 16;
#pragma unroll
        for (int n = 0; n < 16; n++) orow[n] = v[n] - mx - l;
    }
}

// ================= host =================
template <typename T>
static T* sym(const void* symbol) {
    void* p = nullptr;
    cudaGetSymbolAddress(&p, symbol);
    return (T*)p;
}

extern "C" void kernel_launch(void* const* d_in, const int* in_sizes, int n_in,
                              void* d_out, int out_size) {
    const float* x     = (const float*)d_in[0];
    const int*   ei    = (const int*)  d_in[1];
    const int*   et    = (const int*)  d_in[2];
    const float* relW  = (const float*)d_in[3];
    const float* rootW = (const float*)d_in[4];
    const float* bias  = (const float*)d_in[5];
    const float* fc1w  = (const float*)d_in[6];
    const float* fc1b  = (const float*)d_in[7];
    const float* fc2w  = (const float*)d_in[8];
    const float* fc2b  = (const float*)d_in[9];
    float* out = (float*)d_out;

    __nv_bfloat16* xhi = sym<__nv_bfloat16>(g_xhi);
    __nv_bfloat16* xlo = sym<__nv_bfloat16>(g_xlo);
    __nv_bfloat16* ahi = sym<__nv_bfloat16>(g_agghi);
    __nv_bfloat16* alo = sym<__nv_bfloat16>(g_agglo);
    __nv_bfloat16* hhi = sym<__nv_bfloat16>(g_hhi);
    __nv_bfloat16* hlo = sym<__nv_bfloat16>(g_hlo);
    __nv_bfloat16* ehi = sym<__nv_bfloat16>(g_ehi);
    __nv_bfloat16* elo = sym<__nv_bfloat16>(g_elo);
    __nv_bfloat16* Bhi = sym<__nv_bfloat16>(g_Bhi);
    __nv_bfloat16* Blo = sym<__nv_bfloat16>(g_Blo);
    float* f1 = sym<float>(g_f1);

    cudaFuncSetAttribute(gemm_mma, cudaFuncAttributeMaxDynamicSharedMemorySize, SMEM_BYTES);

    const size_t GB = 16 * TILE_ELEMS;   // B elems per gemm

    // CSR build
    zero_int_kernel<<<(NBKT + 255) / 256, 256>>>();
    hist_kernel<<<(EE + 255) / 256, 256>>>(ei, et);
    scan_kernel<<<1, 1024>>>();
    scatter_kernel<<<(EE + 255) / 256, 256>>>(ei, et);

    // conversions into tiled layout
    conv_B<<<(5 * 16 * 1024 + 255) / 256, 256>>>(relW, rootW, fc1w);
    conv_x<<<(NN * 32 + 255) / 256, 256>>>(x);

    const dim3 ggrid2(2 * NBLK, 2);
    const dim3 ggrid1(NBLK, 2);
    const int aggBlocks = (2 * NN * 32 + 255) / 256;

    // stage A: convs {0,2} on x
    agg_csr<<<aggBlocks, 256>>>(xhi, xlo, xhi, xlo, 0, 2, ahi, alo);
    gemm_mma<<<ggrid2, 256, SMEM_BYTES>>>(
        ahi, alo, xhi, xlo, /*a2_global=*/0,
        Bhi + 0 * GB, Blo + 0 * GB, bias + 0 * 256,
        Bhi + 2 * GB, Blo + 2 * GB, bias + 2 * 256,
        nullptr, hhi, hlo);

    // stage B: convs {1,3} on stage-A halves
    agg_csr<<<aggBlocks, 256>>>(hhi, hlo, hhi + HALF_OFF, hlo + HALF_OFF, 1, 3, ahi, alo);
    gemm_mma<<<ggrid2, 256, SMEM_BYTES>>>(
        ahi, alo, hhi, hlo, /*a2_global=*/1,
        Bhi + 1 * GB, Blo + 1 * GB, bias + 1 * 256,
        Bhi + 3 * GB, Blo + 3 * GB, bias + 3 * 256,
        nullptr, ehi, elo);

    // fc1: [e0 | e1] -> f1 (f32, relu)
    gemm_mma<<<ggrid1, 256, SMEM_BYTES>>>(
        ehi, elo, ehi + HALF_OFF, elo + HALF_OFF, /*a2_global=*/0,
        Bhi + 4 * GB, Blo + 4 * GB, fc1b,
        Bhi + 4 * GB, Blo + 4 * GB, fc1b,
        f1, nullptr, nullptr);

    // fc2 + log_softmax
    fc2_lsm_kernel<<<(NN + 3) / 4, 128>>>(f1, fc2w, fc2b, out, NN);
}